// round 2
// baseline (speedup 1.0000x reference)
#include <cuda_runtime.h>
#include <math.h>

#define BATCH 2
#define CIN   128
#define TT    5
#define TC    4
#define HH    48
#define WW    48
#define HW    2304
#define HCH   64

// Scratch (device globals -- no allocation allowed)
__device__ float g_q  [BATCH*HW*HCH];        // [b][p][h]
__device__ float g_phi[BATCH*TC*HW*HCH];     // [b][t][p][h]
__device__ float g_g  [BATCH*TC*HW*HCH];     // [b][t][p][h]
__device__ float g_y  [BATCH*HW*HCH];        // flat [b][p*64+k]
__device__ int   g_offT[12544];              // scramble gather table

// ---------------------------------------------------------------------------
// offT init: i = k*64+j -> element (h,t,dy,dx) of per-pixel flat [64][4][7][7]
// offT[i] = (t*64+h)*141 + dy*14 + dx   (smem offset, pixel part added later)
// ---------------------------------------------------------------------------
__global__ void offt_init_kernel()
{
    int i = blockIdx.x*256 + threadIdx.x;
    if (i < 12544) {
        int h  = i / 196;
        int r  = i - h*196;
        int t  = r / 49;
        int q  = r - t*49;
        int dy = q / 7;
        int dx = q - dy*7;
        g_offT[i] = (t*64 + h)*141 + dy*14 + dx;
    }
}

// ---------------------------------------------------------------------------
// Kernel 1: projections.  grid (18, 5, 2), block 512, dyn smem 135168 B
// ---------------------------------------------------------------------------
__global__ void proj_kernel(const float* __restrict__ x,
                            const float* __restrict__ w_theta,
                            const float* __restrict__ w_phi,
                            const float* __restrict__ w_g)
{
    extern __shared__ float sm[];
    float* sx = sm;                 // [128 c][128 s]
    float* wA = sm + 128*128;       // [128 c][68]
    float* wB = wA + 128*68;
    const int s0  = blockIdx.x * 128;
    const int f   = blockIdx.y;
    const int b   = blockIdx.z;
    const int tid = threadIdx.x;

    for (int i = tid; i < 128*128; i += 512) {
        int c = i >> 7, s = i & 127;
        sx[i] = x[((b*CIN + c)*TT + f)*HW + s0 + s];
    }
    const float* wsrc = (f == 0) ? w_theta : w_phi;
    for (int i = tid; i < HCH*CIN; i += 512) {
        int h = i >> 7, c = i & 127;
        wA[c*68 + h] = wsrc[i];
    }
    if (f > 0) {
        for (int i = tid; i < HCH*CIN; i += 512) {
            int h = i >> 7, c = i & 127;
            wB[c*68 + h] = w_g[i];
        }
    }
    __syncthreads();

    const int pxg = tid & 31;
    const int hg  = tid >> 5;
    float accA[4][4] = {};
    if (f == 0) {
        #pragma unroll 4
        for (int c = 0; c < 128; c++) {
            float4 xv = *(const float4*)(sx + c*128 + pxg*4);
            float4 wa = *(const float4*)(wA + c*68 + hg*4);
            float xs[4]  = {xv.x, xv.y, xv.z, xv.w};
            float was[4] = {wa.x, wa.y, wa.z, wa.w};
            #pragma unroll
            for (int j = 0; j < 4; j++)
                #pragma unroll
                for (int i = 0; i < 4; i++)
                    accA[j][i] = fmaf(was[j], xs[i], accA[j][i]);
        }
        #pragma unroll
        for (int i = 0; i < 4; i++) {
            int s = s0 + pxg*4 + i;
            float4 v = make_float4(accA[0][i], accA[1][i], accA[2][i], accA[3][i]);
            *(float4*)(g_q + (b*HW + s)*HCH + hg*4) = v;
        }
    } else {
        float accB[4][4] = {};
        #pragma unroll 2
        for (int c = 0; c < 128; c++) {
            float4 xv = *(const float4*)(sx + c*128 + pxg*4);
            float4 wa = *(const float4*)(wA + c*68 + hg*4);
            float4 wb = *(const float4*)(wB + c*68 + hg*4);
            float xs[4]  = {xv.x, xv.y, xv.z, xv.w};
            float was[4] = {wa.x, wa.y, wa.z, wa.w};
            float wbs[4] = {wb.x, wb.y, wb.z, wb.w};
            #pragma unroll
            for (int j = 0; j < 4; j++)
                #pragma unroll
                for (int i = 0; i < 4; i++) {
                    accA[j][i] = fmaf(was[j], xs[i], accA[j][i]);
                    accB[j][i] = fmaf(wbs[j], xs[i], accB[j][i]);
                }
        }
        const int t = f - 1;
        #pragma unroll
        for (int i = 0; i < 4; i++) {
            int s = s0 + pxg*4 + i;
            float4 va = make_float4(accA[0][i], accA[1][i], accA[2][i], accA[3][i]);
            float4 vb = make_float4(accB[0][i], accB[1][i], accB[2][i], accB[3][i]);
            *(float4*)(g_phi + ((b*TC + t)*HW + s)*HCH + hg*4) = va;
            *(float4*)(g_g   + ((b*TC + t)*HW + s)*HCH + hg*4) = vb;
        }
    }
}

// ---------------------------------------------------------------------------
// Kernel 2: attention with scrambled-V gather.
// grid (6,12,2), block 1024 (32 warps = 4x8 pixel tile).
// Smem layout (floats):
//   [0, 36096)            g halos, channel-major [t][64][141]
//   [36096, 48640)        UNION: phi [140][68] (pass1) / offT int[12544] (pass2)
//   [48640, 55040)        satt [32 warps][200]
//   [55040, 55180)        sgp  int[140] gathered pixel offsets (*64)
// total 55180 floats = 220720 B
// ---------------------------------------------------------------------------
#define SGM_F   0
#define UNI_F   36096
#define SATT_F  48640
#define SGP_F   55040
#define SMEM_F  55180

__global__ void attn_kernel()
{
    extern __shared__ float sm[];
    float* sgm  = sm + SGM_F;
    float* sphi = sm + UNI_F;
    float* satt = sm + SATT_F;
    int*   sgp  = (int*)(sm + SGP_F);

    const int b    = blockIdx.z;
    const int tid  = threadIdx.x;
    const int lane = tid & 31, warp = tid >> 5;
    const int ly = warp >> 3, lx = warp & 7;
    const int py = blockIdx.y*4 + ly;
    const int px = blockIdx.x*8 + lx;
    const int p  = py*WW + px;
    const int warpPos = ly*14 + lx;

    if (tid < 140) {
        int hy = tid / 14, hx = tid - hy*14;
        int gy = min(max((int)blockIdx.y*4 + hy - 3, 0), HH-1);
        int gx = min(max((int)blockIdx.x*8 + hx - 3, 0), WW-1);
        sgp[tid] = (gy*WW + gx)*HCH;
    }
    __syncthreads();

    // ---- load all 4 frames of g halos, channel-major [t][h][141] ----
    const float* gBase = g_g + (size_t)b*TC*HW*HCH;
    for (int i = tid; i < TC*140*64; i += 1024) {
        int h  = i & 63;
        int pr = i >> 6;
        int pos = pr % 140;
        int t   = pr / 140;
        sgm[(t*64 + h)*141 + pos] = gBase[t*HW*HCH + sgp[pos] + h];
    }

    // ---- q for this pixel ----
    const float* qb = g_q + (b*HW + p)*HCH;
    const int c   = lane & 7;    // channel chunk within key group
    const int sub = lane >> 3;   // key within group of 4
    float4 qv0 = *(const float4*)(qb + c*4);
    float4 qv1 = *(const float4*)(qb + c*4 + 32);
    float  q0r = qb[lane], q1r = qb[lane + 32];

    // ---- pass 1: scores (phi, unscrambled) ----
    const float* pBase = g_phi + (size_t)b*TC*HW*HCH;
    for (int t = 0; t < TC; t++) {
        __syncthreads();   // previous frame's phi reads done
        for (int i = tid; i < 140*16; i += 1024) {
            int c4 = i & 15, pos = i >> 4;
            *(float4*)(sphi + pos*68 + c4*4) =
                *(const float4*)(pBase + t*HW*HCH + sgp[pos] + c4*4);
        }
        __syncthreads();

        #pragma unroll
        for (int g2 = 0; g2 < 12; g2++) {
            int q  = g2*4 + sub;
            int dy = q / 7, dx = q - dy*7;
            int pos = warpPos + dy*14 + dx;
            const float4* pr4 = (const float4*)(sphi + pos*68);
            float4 p0 = pr4[c];
            float4 p1 = pr4[8 + c];
            float s = qv0.x*p0.x + qv0.y*p0.y + qv0.z*p0.z + qv0.w*p0.w
                    + qv1.x*p1.x + qv1.y*p1.y + qv1.z*p1.z + qv1.w*p1.w;
            s += __shfl_xor_sync(0xffffffffu, s, 4);
            s += __shfl_xor_sync(0xffffffffu, s, 2);
            s += __shfl_xor_sync(0xffffffffu, s, 1);
            if (c == 0) satt[warp*200 + t*49 + q] = s * 8.0f;
        }
        // leftover key q=48 (dy=6,dx=6)
        {
            int pos = warpPos + 90;
            float s = q0r*sphi[pos*68 + lane] + q1r*sphi[pos*68 + lane + 32];
            s += __shfl_xor_sync(0xffffffffu, s, 16);
            s += __shfl_xor_sync(0xffffffffu, s, 8);
            s += __shfl_xor_sync(0xffffffffu, s, 4);
            s += __shfl_xor_sync(0xffffffffu, s, 2);
            s += __shfl_xor_sync(0xffffffffu, s, 1);
            if (lane == 0) satt[warp*200 + t*49 + 48] = s * 8.0f;
        }
    }
    __syncthreads();   // all pass-1 phi reads done; union region free

    // ---- stage offT into smem (aliases phi region) ----
    {
        int4* dst = (int4*)sphi;
        const int4* src = (const int4*)g_offT;
        for (int i = tid; i < 12544/4; i += 1024) dst[i] = src[i];
    }

    // ---- per-warp softmax over 196 raw scores (deferred normalization) ----
    float sv[7];
    float m = -1e30f;
    #pragma unroll
    for (int g2 = 0; g2 < 7; g2++) {
        int k = lane + 32*g2;
        sv[g2] = (k < 196) ? satt[warp*200 + k] : -1e30f;
        m = fmaxf(m, sv[g2]);
    }
    m = fmaxf(m, __shfl_xor_sync(0xffffffffu, m, 16));
    m = fmaxf(m, __shfl_xor_sync(0xffffffffu, m, 8));
    m = fmaxf(m, __shfl_xor_sync(0xffffffffu, m, 4));
    m = fmaxf(m, __shfl_xor_sync(0xffffffffu, m, 2));
    m = fmaxf(m, __shfl_xor_sync(0xffffffffu, m, 1));
    float tot = 0.f;
    #pragma unroll
    for (int g2 = 0; g2 < 7; g2++) {
        int k = lane + 32*g2;
        if (k < 196) {
            float e = __expf(sv[g2] - m);
            satt[warp*200 + k] = e;
            tot += e;
        }
    }
    tot += __shfl_xor_sync(0xffffffffu, tot, 16);
    tot += __shfl_xor_sync(0xffffffffu, tot, 8);
    tot += __shfl_xor_sync(0xffffffffu, tot, 4);
    tot += __shfl_xor_sync(0xffffffffu, tot, 2);
    tot += __shfl_xor_sync(0xffffffffu, tot, 1);
    float inv = 1.0f / tot;

    __syncthreads();   // offT staged

    // ---- pass 2: scrambled-V accumulation ----
    const int* soff = (const int*)sphi;
    float acc0 = 0.f, acc1 = 0.f;
    for (int k = 0; k < 196; k += 4) {
        float4 w4 = *(const float4*)(satt + warp*200 + k);
        float wv[4] = {w4.x, w4.y, w4.z, w4.w};
        #pragma unroll
        for (int u = 0; u < 4; u++) {
            int base = (k + u)*64 + lane;
            int o0 = soff[base];
            int o1 = soff[base + 32];
            acc0 = fmaf(wv[u], sgm[o0 + warpPos], acc0);
            acc1 = fmaf(wv[u], sgm[o1 + warpPos], acc1);
        }
    }
    float* yb = g_y + (b*HW + p)*HCH;
    yb[lane]      = acc0 * inv;
    yb[lane + 32] = acc1 * inv;
}

// ---------------------------------------------------------------------------
// Kernel 3: output projection + residual (handles the y-reshape scramble).
// out[b,c,s] = x[b,c,0,s] + sum_h' w_out[c,h'] * y_flat[b][h'*2304 + s]
// ---------------------------------------------------------------------------
__global__ void out_kernel(const float* __restrict__ x,
                           const float* __restrict__ w_out,
                           float* __restrict__ out)
{
    __shared__ float sy [64*64];
    __shared__ float swt[64*68];
    const int s0  = blockIdx.x * 64;
    const int c0  = blockIdx.y * 64;
    const int b   = blockIdx.z;
    const int tid = threadIdx.x;
    const float* yb = g_y + b*HW*HCH;
    for (int i = tid; i < 4096; i += 256) {
        int hh = i >> 6, s = i & 63;
        sy[i] = yb[hh*HW + s0 + s];
        int cc = i >> 6, h2 = i & 63;
        swt[h2*68 + cc] = w_out[(c0 + cc)*HCH + h2];
    }
    __syncthreads();
    const int sg2 = tid & 15;
    const int cg  = tid >> 4;
    float acc[4][4] = {};
    #pragma unroll 4
    for (int hh = 0; hh < 64; hh++) {
        float4 yv = *(const float4*)(sy  + hh*64 + sg2*4);
        float4 wv = *(const float4*)(swt + hh*68 + cg*4);
        float ys[4] = {yv.x, yv.y, yv.z, yv.w};
        float ws[4] = {wv.x, wv.y, wv.z, wv.w};
        #pragma unroll
        for (int j = 0; j < 4; j++)
            #pragma unroll
            for (int i = 0; i < 4; i++)
                acc[j][i] = fmaf(ws[j], ys[i], acc[j][i]);
    }
    #pragma unroll
    for (int j = 0; j < 4; j++) {
        int cc = c0 + cg*4 + j;
        float4 xv = *(const float4*)(x + (b*CIN + cc)*TT*HW + s0 + sg2*4);
        float4 o  = make_float4(acc[j][0]+xv.x, acc[j][1]+xv.y,
                                acc[j][2]+xv.z, acc[j][3]+xv.w);
        *(float4*)(out + (b*CIN + cc)*HW + s0 + sg2*4) = o;
    }
}

extern "C" void kernel_launch(void* const* d_in, const int* in_sizes, int n_in,
                              void* d_out, int out_size)
{
    const float* x  = (const float*)d_in[0];
    const float* wt = (const float*)d_in[1];
    const float* wp = (const float*)d_in[2];
    const float* wg = (const float*)d_in[3];
    const float* wo = (const float*)d_in[4];
    float* out = (float*)d_out;

    cudaFuncSetAttribute(proj_kernel, cudaFuncAttributeMaxDynamicSharedMemorySize, 135168);
    cudaFuncSetAttribute(attn_kernel, cudaFuncAttributeMaxDynamicSharedMemorySize, SMEM_F*4);

    offt_init_kernel<<<49, 256>>>();
    proj_kernel<<<dim3(18, 5, 2), 512, 135168>>>(x, wt, wp, wg);
    attn_kernel<<<dim3(6, 12, 2), 1024, SMEM_F*4>>>();
    out_kernel<<<dim3(36, 2, 2), 256>>>(x, wo, out);
}